// round 8
// baseline (speedup 1.0000x reference)
#include <cuda_runtime.h>
#include <math.h>

#define T_TOK   65536
#define D_EMB   256
#define H_DIM   64
#define N_EXP   10
#define TILE    32           // tokens per FFN pass
#define CHUNK   64           // tokens per FFN block (2 passes of 32)
#define XS_STR  36           // 32 tokens + 4 pad
#define HS_STR  36
#define NBLK_C  16384
#define NBLK_G  (T_TOK / 32) // 2048 gating blocks

typedef unsigned long long u64;

__device__ __forceinline__ u64 pack2(float lo, float hi) {
    u64 r; asm("mov.b64 %0,{%1,%2};" : "=l"(r) : "f"(lo), "f"(hi)); return r;
}
__device__ __forceinline__ void ffma2(u64& d, u64 a, u64 b) {
    asm("fma.rn.f32x2 %0,%1,%2,%0;" : "+l"(d) : "l"(a), "l"(b));
}
__device__ __forceinline__ u64 add2(u64 a, u64 b) {
    u64 r; asm("add.rn.f32x2 %0,%1,%2;" : "=l"(r) : "l"(a), "l"(b)); return r;
}
__device__ __forceinline__ u64 mul2(u64 a, u64 b) {
    u64 r; asm("mul.rn.f32x2 %0,%1,%2;" : "=l"(r) : "l"(a), "l"(b)); return r;
}
__device__ __forceinline__ float2 unpack2(u64 v) {
    float2 r; asm("mov.b64 {%0,%1},%2;" : "=f"(r.x), "=f"(r.y) : "l"(v)); return r;
}

// ---------------- scratch (zero-initialized at module load) -------------------
__device__ int   g_count[N_EXP];          // zeroed by k_final tail each call
__device__ int   g_bucket[N_EXP * T_TOK];
__device__ float g_gates[T_TOK * 2];
__device__ float g_part [(size_t)T_TOK * 2 * D_EMB];
__device__ float g_kd_part[NBLK_C];
__device__ float g_imp_part[NBLK_G * N_EXP];

// ---------------- kernel A: gating + importance partials ----------------------
__global__ void __launch_bounds__(256) k_gate(const float* __restrict__ x,
                                              const float* __restrict__ wg) {
    __shared__ float wgs[N_EXP * D_EMB];
    __shared__ float impW[8][N_EXP];
    int tid = threadIdx.x;
    for (int i = tid; i < D_EMB * N_EXP; i += 256) {
        int e = i / D_EMB, d = i - e * D_EMB;
        wgs[i] = wg[d * N_EXP + e];
    }
    __syncthreads();

    int warp = tid >> 5, lane = tid & 31;
    int t0 = blockIdx.x * 32 + warp * 4;

    float impL[N_EXP];
#pragma unroll
    for (int e = 0; e < N_EXP; ++e) impL[e] = 0.f;

    for (int r = 0; r < 4; ++r) {
        int t = t0 + r;
        float part[N_EXP];
#pragma unroll
        for (int e = 0; e < N_EXP; ++e) part[e] = 0.f;
#pragma unroll
        for (int dd = 0; dd < 8; ++dd) {
            int d = dd * 32 + lane;
            float xv = x[(size_t)t * D_EMB + d];
#pragma unroll
            for (int e = 0; e < N_EXP; ++e)
                part[e] = fmaf(xv, wgs[e * D_EMB + d], part[e]);
        }
#pragma unroll
        for (int e = 0; e < N_EXP; ++e) {
#pragma unroll
            for (int off = 16; off; off >>= 1)
                part[e] += __shfl_xor_sync(0xffffffffu, part[e], off);
        }
        if (lane == 0) {
            float m0 = -1e30f; int e0 = 0;
#pragma unroll
            for (int e = 0; e < N_EXP; ++e) if (part[e] > m0) { m0 = part[e]; e0 = e; }
            float m1 = -1e30f; int e1 = 0;
#pragma unroll
            for (int e = 0; e < N_EXP; ++e) if (e != e0 && part[e] > m1) { m1 = part[e]; e1 = e; }
            float ex = expf(m1 - m0);
            float s  = 1.f + ex;
            float g0 = 1.f / s;
            float g1 = ex / s;
            g_gates[2 * t]     = g0;
            g_gates[2 * t + 1] = g1;
#pragma unroll
            for (int q = 0; q < N_EXP; ++q) {
                if (q == e0) impL[q] += g0;
                if (q == e1) impL[q] += g1;
            }
            int p0 = atomicAdd(&g_count[e0], 1);
            g_bucket[e0 * T_TOK + p0] = (t << 1);
            int p1 = atomicAdd(&g_count[e1], 1);
            g_bucket[e1 * T_TOK + p1] = (t << 1) | 1;
        }
    }

    if (lane == 0) {
#pragma unroll
        for (int e = 0; e < N_EXP; ++e) impW[warp][e] = impL[e];
    }
    __syncthreads();
    if (tid < N_EXP) {
        float s = 0.f;
#pragma unroll
        for (int w = 0; w < 8; ++w) s += impW[w][tid];
        g_imp_part[blockIdx.x * N_EXP + tid] = s;
    }
}

// ---------------- kernel B: expert-grouped FFN --------------------------------
// 32-token passes, ~46 KB static smem -> 4 blocks/SM (8 warps/SMSP).
// Per thread: 2 tokens (tg=tid&15) x 4 h/o (hg=tid>>4). Weights via broadcast LDG.
__global__ void __launch_bounds__(256, 4) k_ffn(const float* __restrict__ x,
                                                const float* __restrict__ w1,
                                                const float* __restrict__ b1,
                                                const float* __restrict__ w2,
                                                const float* __restrict__ b2) {
    int e = blockIdx.y;
    int n_total = g_count[e];
    int base = blockIdx.x * CHUNK;
    if (base >= n_total) return;

    __shared__ float xs[D_EMB * XS_STR];   // [256][36] transposed x (36.9 KB)
    __shared__ float hs[H_DIM * HS_STR];   // [64][36]  transposed h (9.2 KB)
    __shared__ float gsh[TILE];
    __shared__ int   ash[TILE];

    int tid = threadIdx.x;
    int tg = tid & 15;    // token pair: tokens tg*2, tg*2+1
    int hg = tid >> 4;    // 0..15 -> h/o group of 4

    const float* w1e = w1 + (size_t)e * D_EMB * H_DIM + hg * 4;
    const float* w2e = w2 + (size_t)e * H_DIM * D_EMB;

    float2 b1a = *(const float2*)(b1 + e * H_DIM + hg * 4);
    float2 b1b = *(const float2*)(b1 + e * H_DIM + hg * 4 + 2);

    int s_stage  = tid & 31;
    int dq_stage = tid >> 5;   // 0..7

    for (int p = 0; p < CHUNK / TILE; ++p) {
        int tbase = base + p * TILE;
        if (tbase >= n_total) break;
        int nt = min(TILE, n_total - tbase);

        __syncthreads();  // previous pass fully consumed
        if (tid < TILE) {
            if (tid < nt) {
                int a = g_bucket[e * T_TOK + tbase + tid];
                ash[tid] = a;
                gsh[tid] = g_gates[a];
            } else { ash[tid] = -1; gsh[tid] = 0.f; }
        }
        __syncthreads();

        // stage x tile transposed: thread (s_stage, dq_stage)
        {
            int a = ash[s_stage];
            const float4* xrow = (a >= 0)
                ? (const float4*)(x + (size_t)(a >> 1) * D_EMB) : (const float4*)0;
#pragma unroll
            for (int it = 0; it < 8; ++it) {
                int d4 = it * 8 + dq_stage;   // 0..63
                float4 v = make_float4(0.f, 0.f, 0.f, 0.f);
                if (a >= 0) v = xrow[d4];
                xs[(d4 * 4 + 0) * XS_STR + s_stage] = v.x;
                xs[(d4 * 4 + 1) * XS_STR + s_stage] = v.y;
                xs[(d4 * 4 + 2) * XS_STR + s_stage] = v.z;
                xs[(d4 * 4 + 3) * XS_STR + s_stage] = v.w;
            }
        }
        __syncthreads();

        // ---- fc1: 2tok x 4h per thread ----
        {
            u64 acc00 = 0, acc01 = 0, acc10 = 0, acc11 = 0;
#pragma unroll 8
            for (int d = 0; d < D_EMB; ++d) {
                float2 xv = *(const float2*)(xs + d * XS_STR + tg * 2);
                u64 a0 = pack2(xv.x, xv.x);
                u64 a1 = pack2(xv.y, xv.y);
                ulonglong2 w = *(const ulonglong2*)(w1e + (size_t)d * H_DIM);
                ffma2(acc00, a0, w.x); ffma2(acc01, a0, w.y);
                ffma2(acc10, a1, w.x); ffma2(acc11, a1, w.y);
            }
            float2 h;
            int hb = hg * 4;
            h = unpack2(acc00);
            hs[(hb + 0) * HS_STR + tg * 2 + 0] = fmaxf(h.x + b1a.x, 0.f);
            hs[(hb + 1) * HS_STR + tg * 2 + 0] = fmaxf(h.y + b1a.y, 0.f);
            h = unpack2(acc01);
            hs[(hb + 2) * HS_STR + tg * 2 + 0] = fmaxf(h.x + b1b.x, 0.f);
            hs[(hb + 3) * HS_STR + tg * 2 + 0] = fmaxf(h.y + b1b.y, 0.f);
            h = unpack2(acc10);
            hs[(hb + 0) * HS_STR + tg * 2 + 1] = fmaxf(h.x + b1a.x, 0.f);
            hs[(hb + 1) * HS_STR + tg * 2 + 1] = fmaxf(h.y + b1a.y, 0.f);
            h = unpack2(acc11);
            hs[(hb + 2) * HS_STR + tg * 2 + 1] = fmaxf(h.x + b1b.x, 0.f);
            hs[(hb + 3) * HS_STR + tg * 2 + 1] = fmaxf(h.y + b1b.y, 0.f);
        }
        __syncthreads();

        // ---- fc2: part = gate * (h @ W2 + b2), 4 output chunks of 64 ----
        int a0i = ash[tg * 2], a1i = ash[tg * 2 + 1];
        float g0 = gsh[tg * 2], g1 = gsh[tg * 2 + 1];
        u64 gp0 = pack2(g0, g0), gp1 = pack2(g1, g1);

#pragma unroll 1
        for (int oc = 0; oc < 4; ++oc) {
            int o = oc * 64 + hg * 4;
            const float* w2p = w2e + o;
            u64 acc00 = 0, acc01 = 0, acc10 = 0, acc11 = 0;
#pragma unroll 8
            for (int k = 0; k < H_DIM; ++k) {
                float2 hv = *(const float2*)(hs + k * HS_STR + tg * 2);
                u64 a0 = pack2(hv.x, hv.x);
                u64 a1 = pack2(hv.y, hv.y);
                ulonglong2 w = *(const ulonglong2*)(w2p + (size_t)k * D_EMB);
                ffma2(acc00, a0, w.x); ffma2(acc01, a0, w.y);
                ffma2(acc10, a1, w.x); ffma2(acc11, a1, w.y);
            }
            ulonglong2 bb = *(const ulonglong2*)(b2 + e * D_EMB + o);
            if (a0i >= 0) {
                ulonglong2 r;
                r.x = mul2(add2(acc00, bb.x), gp0);
                r.y = mul2(add2(acc01, bb.y), gp0);
                *(ulonglong2*)(g_part + (size_t)a0i * D_EMB + o) = r;
            }
            if (a1i >= 0) {
                ulonglong2 r;
                r.x = mul2(add2(acc10, bb.x), gp1);
                r.y = mul2(add2(acc11, bb.y), gp1);
                *(ulonglong2*)(g_part + (size_t)a1i * D_EMB + o) = r;
            }
        }
    }
}

// ---------------- kernel C: combine -------------------------------------------
__global__ void __launch_bounds__(256) k_combine(float* __restrict__ out) {
    __shared__ float red[256];
    int tid = threadIdx.x;
    size_t f4 = (size_t)blockIdx.x * 256 + tid;
    size_t t  = f4 >> 6;
    int    q  = (int)(f4 & 63);

    float4 a = *((const float4*)(g_part + (t * 2)     * D_EMB) + q);
    float4 b = *((const float4*)(g_part + (t * 2 + 1) * D_EMB) + q);
    float4 y;
    y.x = a.x + b.x; y.y = a.y + b.y; y.z = a.z + b.z; y.w = a.w + b.w;

    float kd = fabsf(y.x) + fabsf(y.y) + fabsf(y.z) + fabsf(y.w);

    float4 o;
    o.x = y.x * 0.5f; o.y = y.y * 0.5f; o.z = y.z * 0.5f; o.w = y.w * 0.5f;
    ((float4*)out)[f4] = o;

    red[tid] = kd;
    __syncthreads();
    for (int s = 128; s; s >>= 1) {
        if (tid < s) red[tid] += red[tid + s];
        __syncthreads();
    }
    if (tid == 0) g_kd_part[blockIdx.x] = red[0];
}

// ---------------- kernel D: finalize loss + reset counters ---------------------
__global__ void __launch_bounds__(256) k_final(float* __restrict__ out, int out_size) {
    __shared__ float red[256];
    __shared__ float impS[N_EXP * 256];
    int tid = threadIdx.x;

    float s = 0.f;
    for (int i = tid; i < NBLK_C; i += 256) s += g_kd_part[i];
    red[tid] = s;
    __syncthreads();
    for (int st = 128; st; st >>= 1) {
        if (tid < st) red[tid] += red[tid + st];
        __syncthreads();
    }
    float kd_total = red[0];
    __syncthreads();

    float imp[N_EXP];
#pragma unroll
    for (int e = 0; e < N_EXP; ++e) imp[e] = 0.f;
    for (int i = tid; i < NBLK_G; i += 256) {
#pragma unroll
        for (int e = 0; e < N_EXP; ++e)
            imp[e] += g_imp_part[i * N_EXP + e];
    }
#pragma unroll
    for (int e = 0; e < N_EXP; ++e) impS[e * 256 + tid] = imp[e];
    __syncthreads();
    for (int st = 128; st; st >>= 1) {
        if (tid < st)
#pragma unroll
            for (int e = 0; e < N_EXP; ++e)
                impS[e * 256 + tid] += impS[e * 256 + tid + st];
        __syncthreads();
    }

    if (tid == 0) {
        float iv[N_EXP], lv[N_EXP];
        float si = 0.f, sl = 0.f;
#pragma unroll
        for (int e = 0; e < N_EXP; ++e) {
            iv[e] = impS[e * 256];
            lv[e] = (float)g_count[e];
            si += iv[e]; sl += lv[e];
        }
        float mi = si / (float)N_EXP, ml = sl / (float)N_EXP;
        float vi = 0.f, vl = 0.f;
#pragma unroll
        for (int e = 0; e < N_EXP; ++e) {
            float di = iv[e] - mi; vi += di * di;
            float dl = lv[e] - ml; vl += dl * dl;
        }
        vi /= (float)(N_EXP - 1);
        vl /= (float)(N_EXP - 1);
        float aux = vi / (mi * mi + 1e-10f) + vl / (ml * ml + 1e-10f);
        float kd  = kd_total / (float)((size_t)T_TOK * D_EMB);
        if (out_size > T_TOK * D_EMB)
            out[(size_t)T_TOK * D_EMB] = aux + kd;
    }

    __syncthreads();
    if (tid < N_EXP) g_count[tid] = 0;
}

// ---------------- launch --------------------------------------------------------
extern "C" void kernel_launch(void* const* d_in, const int* in_sizes, int n_in,
                              void* d_out, int out_size) {
    const float* x  = (const float*)d_in[0];
    const float* wg = (const float*)d_in[1];
    const float* w1 = (const float*)d_in[2];
    const float* b1 = (const float*)d_in[3];
    const float* w2 = (const float*)d_in[4];
    const float* b2 = (const float*)d_in[5];
    float* out = (float*)d_out;

    k_gate<<<NBLK_G, 256>>>(x, wg);
    dim3 gB(T_TOK / CHUNK, N_EXP);
    k_ffn<<<gB, 256>>>(x, w1, b1, w2, b2);
    k_combine<<<NBLK_C, 256>>>(out);
    k_final<<<1, 256>>>(out, out_size);
}

// round 11
// speedup vs baseline: 2.0441x; 2.0441x over previous
#include <cuda_runtime.h>
#include <cuda_bf16.h>
#include <math.h>
#include <stdint.h>

#define T_TOK   65536
#define D_EMB   256
#define H_DIM   64
#define N_EXP   10
#define MTOK    128
#define NBLK_C  16384
#define NBLK_G  (T_TOK / 32)

// smem element strides (floats->bf16 elems). All = 4 banks shift per row.
#define SA1 264            // x tile rows: 256 k + 8 pad
#define SB1 72             // w1 rows (k-major): 64 n + 8 pad
#define SA2 72             // h tile rows: 64 k + 8 pad
#define SB2 264            // w2 rows (k-major): 256 n + 8 pad

// byte offsets inside the 1024-aligned dynamic smem tile
#define A1HI 0
#define A1LO 67584         // 128*264*2
#define B1HI 135168
#define B1LO 172032        // +256*72*2
// phase 2 (reuses phase-1 space after a syncthreads)
#define B2HI 0
#define B2LO 33792         // 64*264*2
#define A2HI 135168
#define A2LO 153600        // +128*72*2
#define ASH_OFF 208896
#define GSH_OFF 209408
#define SMEM_FFN (209920 + 1024)

// ---------------- scratch ------------------------------------------------------
__device__ int   g_count[N_EXP];
__device__ int   g_bucket[N_EXP * T_TOK];
__device__ float g_gates[T_TOK * 2];
__device__ float g_part [(size_t)T_TOK * 2 * D_EMB];
__device__ float g_kd_part[NBLK_C];
__device__ float g_imp_part[NBLK_G * N_EXP];

// ---------------- helpers --------------------------------------------------------
__device__ __forceinline__ uint32_t smem_u32(const void* p) {
    uint32_t a;
    asm("{ .reg .u64 t; cvta.to.shared.u64 t, %1; cvt.u32.u64 %0, t; }" : "=r"(a) : "l"(p));
    return a;
}
__device__ __forceinline__ uint32_t bf16x2_rn(float lo, float hi) {
    uint32_t r;
    asm("cvt.rn.bf16x2.f32 %0,%1,%2;" : "=r"(r) : "f"(hi), "f"(lo));
    return r;
}
// split (f0,f1) -> hi bf16x2 (f0 in low half) and lo bf16x2 residuals
__device__ __forceinline__ void split2(float f0, float f1, uint32_t& hp, uint32_t& lp) {
    hp = bf16x2_rn(f0, f1);
    float r0 = f0 - __uint_as_float(hp << 16);
    float r1 = f1 - __uint_as_float(hp & 0xFFFF0000u);
    lp = bf16x2_rn(r0, r1);
}
__device__ __forceinline__ void sts64(uint32_t addr, uint32_t a, uint32_t b) {
    asm volatile("st.shared.v2.b32 [%0], {%1,%2};" :: "r"(addr), "r"(a), "r"(b) : "memory");
}
__device__ __forceinline__ void sts32(uint32_t addr, uint32_t v) {
    asm volatile("st.shared.b32 [%0], %1;" :: "r"(addr), "r"(v) : "memory");
}
__device__ __forceinline__ void ldm4(uint32_t* r, uint32_t a) {
    asm volatile("ldmatrix.sync.aligned.m8n8.x4.shared.b16 {%0,%1,%2,%3}, [%4];"
                 : "=r"(r[0]), "=r"(r[1]), "=r"(r[2]), "=r"(r[3]) : "r"(a));
}
__device__ __forceinline__ void ldm4t(uint32_t* r, uint32_t a) {
    asm volatile("ldmatrix.sync.aligned.m8n8.x4.trans.shared.b16 {%0,%1,%2,%3}, [%4];"
                 : "=r"(r[0]), "=r"(r[1]), "=r"(r[2]), "=r"(r[3]) : "r"(a));
}
__device__ __forceinline__ void mma_bf16(float* c, const uint32_t* a, uint32_t b0, uint32_t b1) {
    asm volatile(
        "mma.sync.aligned.m16n8k16.row.col.f32.bf16.bf16.f32 "
        "{%0,%1,%2,%3},{%4,%5,%6,%7},{%8,%9},{%0,%1,%2,%3};"
        : "+f"(c[0]), "+f"(c[1]), "+f"(c[2]), "+f"(c[3])
        : "r"(a[0]), "r"(a[1]), "r"(a[2]), "r"(a[3]), "r"(b0), "r"(b1));
}

// ---------------- kernel A: gating + importance partials (proven) ---------------
__global__ void __launch_bounds__(256) k_gate(const float* __restrict__ x,
                                              const float* __restrict__ wg) {
    __shared__ float wgs[N_EXP * D_EMB];
    __shared__ float impW[8][N_EXP];
    int tid = threadIdx.x;
    for (int i = tid; i < D_EMB * N_EXP; i += 256) {
        int e = i / D_EMB, d = i - e * D_EMB;
        wgs[i] = wg[d * N_EXP + e];
    }
    __syncthreads();

    int warp = tid >> 5, lane = tid & 31;
    int t0 = blockIdx.x * 32 + warp * 4;

    float impL[N_EXP];
#pragma unroll
    for (int e = 0; e < N_EXP; ++e) impL[e] = 0.f;

    for (int r = 0; r < 4; ++r) {
        int t = t0 + r;
        float part[N_EXP];
#pragma unroll
        for (int e = 0; e < N_EXP; ++e) part[e] = 0.f;
#pragma unroll
        for (int dd = 0; dd < 8; ++dd) {
            int d = dd * 32 + lane;
            float xv = x[(size_t)t * D_EMB + d];
#pragma unroll
            for (int e = 0; e < N_EXP; ++e)
                part[e] = fmaf(xv, wgs[e * D_EMB + d], part[e]);
        }
#pragma unroll
        for (int e = 0; e < N_EXP; ++e) {
#pragma unroll
            for (int off = 16; off; off >>= 1)
                part[e] += __shfl_xor_sync(0xffffffffu, part[e], off);
        }
        if (lane == 0) {
            float m0 = -1e30f; int e0 = 0;
#pragma unroll
            for (int e = 0; e < N_EXP; ++e) if (part[e] > m0) { m0 = part[e]; e0 = e; }
            float m1 = -1e30f; int e1 = 0;
#pragma unroll
            for (int e = 0; e < N_EXP; ++e) if (e != e0 && part[e] > m1) { m1 = part[e]; e1 = e; }
            float ex = expf(m1 - m0);
            float s  = 1.f + ex;
            float g0 = 1.f / s;
            float g1 = ex / s;
            g_gates[2 * t]     = g0;
            g_gates[2 * t + 1] = g1;
#pragma unroll
            for (int q = 0; q < N_EXP; ++q) {
                if (q == e0) impL[q] += g0;
                if (q == e1) impL[q] += g1;
            }
            int p0 = atomicAdd(&g_count[e0], 1);
            g_bucket[e0 * T_TOK + p0] = (t << 1);
            int p1 = atomicAdd(&g_count[e1], 1);
            g_bucket[e1 * T_TOK + p1] = (t << 1) | 1;
        }
    }

    if (lane == 0) {
#pragma unroll
        for (int e = 0; e < N_EXP; ++e) impW[warp][e] = impL[e];
    }
    __syncthreads();
    if (tid < N_EXP) {
        float s = 0.f;
#pragma unroll
        for (int w = 0; w < 8; ++w) s += impW[w][tid];
        g_imp_part[blockIdx.x * N_EXP + tid] = s;
    }
}

// ---------------- kernel B: mma.sync split-bf16 FFN ------------------------------
// Block = 1 expert x 128 tokens, 256 thr (8 warps x 16 token-rows).
// GEMM1: D1[128,64] = X[128,256] @ W1[256,64]   (bf16 split, 3 terms)
// GEMM2: D2[128,256] = H[128,64] @ W2[64,256]
__global__ void __launch_bounds__(256, 1) k_ffn(const float* __restrict__ x,
                                                const float* __restrict__ w1,
                                                const float* __restrict__ b1,
                                                const float* __restrict__ w2,
                                                const float* __restrict__ b2) {
    int e = blockIdx.y;
    int n_total = g_count[e];
    int base = blockIdx.x * MTOK;
    if (base >= n_total) return;

    extern __shared__ char smraw[];
    char* bp = (char*)(((uintptr_t)smraw + 1023) & ~(uintptr_t)1023);
    uint32_t tb = smem_u32(bp);
    int*   ash = (int*)(bp + ASH_OFF);
    float* gsh = (float*)(bp + GSH_OFF);

    int tid  = threadIdx.x;
    int lane = tid & 31;
    int R    = (tid >> 5) * 16;          // warp's token-row base

    // ---- stage assignments ----
    if (tid < MTOK) {
        int a = (base + tid < n_total) ? g_bucket[e * T_TOK + base + tid] : -1;
        ash[tid] = a;
        gsh[tid] = (a >= 0) ? g_gates[a] : 0.f;
    }
    __syncthreads();

    // ---- stage A1 (x rows, split): thread -> row tid>>1, half tid&1 ----
    {
        int row = tid >> 1;
        int ks  = (tid & 1) * 128;
        int a   = ash[row];
        const float4* xr = (a >= 0) ? (const float4*)(x + (size_t)(a >> 1) * D_EMB + ks)
                                    : (const float4*)0;
        uint32_t dst = tb + A1HI + ((uint32_t)(row * SA1 + ks) << 1);
#pragma unroll 8
        for (int i = 0; i < 32; ++i) {
            float4 v = (a >= 0) ? xr[i] : make_float4(0.f, 0.f, 0.f, 0.f);
            uint32_t h0, l0, h1, l1;
            split2(v.x, v.y, h0, l0);
            split2(v.z, v.w, h1, l1);
            sts64(dst + i * 8, h0, h1);
            sts64(dst + i * 8 + (A1LO - A1HI), l0, l1);
        }
    }

    // ---- stage B1 = w1[e] as [k=256][n=64] bf16 hi/lo (natural layout) ----
    {
        const float4* w1g = (const float4*)(w1 + (size_t)e * D_EMB * H_DIM);
#pragma unroll 4
        for (int i = tid; i < 4096; i += 256) {
            int k  = i >> 4;
            int n4 = (i & 15) * 4;
            float4 v = w1g[i];
            uint32_t h0, l0, h1, l1;
            split2(v.x, v.y, h0, l0);
            split2(v.z, v.w, h1, l1);
            uint32_t dst = tb + B1HI + ((uint32_t)(k * SB1 + n4) << 1);
            sts64(dst, h0, h1);
            sts64(dst + (B1LO - B1HI), l0, l1);
        }
    }
    __syncthreads();

    // ldmatrix lane geometry
    int rowA = R + (lane & 7) + ((lane >> 3) & 1) * 8;   // A frag row
    int kAo  = (lane >> 4) * 8;                          // A frag k offset
    int kBo  = (lane & 7) + ((lane >> 3) & 1) * 8;       // B frag k row
    int nBo  = (lane >> 4) * 8;                          // B frag n offset

    // ---- GEMM1 ----
    float acc1[8][4];
#pragma unroll
    for (int j = 0; j < 8; ++j)
#pragma unroll
        for (int q = 0; q < 4; ++q) acc1[j][q] = 0.f;

#pragma unroll 2
    for (int s = 0; s < 16; ++s) {
        uint32_t ah[4], al[4];
        uint32_t aAddr = tb + A1HI + ((uint32_t)(rowA * SA1 + s * 16 + kAo) << 1);
        ldm4(ah, aAddr);
        ldm4(al, aAddr + (A1LO - A1HI));
#pragma unroll
        for (int jp = 0; jp < 4; ++jp) {
            uint32_t bh[4], bl[4];
            uint32_t bAddr = tb + B1HI + ((uint32_t)((s * 16 + kBo) * SB1 + jp * 16 + nBo) << 1);
            ldm4t(bh, bAddr);
            ldm4t(bl, bAddr + (B1LO - B1HI));
            mma_bf16(acc1[2 * jp],     ah, bh[0], bh[1]);
            mma_bf16(acc1[2 * jp],     ah, bl[0], bl[1]);
            mma_bf16(acc1[2 * jp],     al, bh[0], bh[1]);
            mma_bf16(acc1[2 * jp + 1], ah, bh[2], bh[3]);
            mma_bf16(acc1[2 * jp + 1], ah, bl[2], bl[3]);
            mma_bf16(acc1[2 * jp + 1], al, bh[2], bh[3]);
        }
    }
    __syncthreads();   // A1/B1 no longer needed; smem reused below

    // ---- epilogue1: h = relu(D1 + b1) -> A2 (split bf16) ----
    {
        int g = lane >> 2, t = lane & 3;
        int r0 = R + g, r1 = R + g + 8;
#pragma unroll
        for (int j = 0; j < 8; ++j) {
            int h0 = 8 * j + 2 * t;
            float2 bv = *(const float2*)(b1 + e * H_DIM + h0);
            float v0 = fmaxf(acc1[j][0] + bv.x, 0.f);
            float v1 = fmaxf(acc1[j][1] + bv.y, 0.f);
            float v2 = fmaxf(acc1[j][2] + bv.x, 0.f);
            float v3 = fmaxf(acc1[j][3] + bv.y, 0.f);
            uint32_t hp, lp;
            split2(v0, v1, hp, lp);
            uint32_t d0 = tb + A2HI + ((uint32_t)(r0 * SA2 + h0) << 1);
            sts32(d0, hp);
            sts32(d0 + (A2LO - A2HI), lp);
            split2(v2, v3, hp, lp);
            uint32_t d1 = tb + A2HI + ((uint32_t)(r1 * SA2 + h0) << 1);
            sts32(d1, hp);
            sts32(d1 + (A2LO - A2HI), lp);
        }
    }

    // ---- stage B2 = w2[e] as [k=64][n=256] bf16 hi/lo ----
    {
        const float4* w2g = (const float4*)(w2 + (size_t)e * H_DIM * D_EMB);
#pragma unroll 4
        for (int i = tid; i < 4096; i += 256) {
            int k  = i >> 6;
            int o4 = (i & 63) * 4;
            float4 v = w2g[i];
            uint32_t h0, l0, h1, l1;
            split2(v.x, v.y, h0, l0);
            split2(v.z, v.w, h1, l1);
            uint32_t dst = tb + B2HI + ((uint32_t)(k * SB2 + o4) << 1);
            sts64(dst, h0, h1);
            sts64(dst + (B2LO - B2HI), l0, l1);
        }
    }
    __syncthreads();

    // ---- GEMM2: A frags (all K=64) resident in registers ----
    uint32_t ah2[4][4], al2[4][4];
#pragma unroll
    for (int s = 0; s < 4; ++s) {
        uint32_t aAddr = tb + A2HI + ((uint32_t)(rowA * SA2 + s * 16 + kAo) << 1);
        ldm4(ah2[s], aAddr);
        ldm4(al2[s], aAddr + (A2LO - A2HI));
    }

    int g = lane >> 2, t = lane & 3;
    int aR0 = ash[R + g], aR1 = ash[R + g + 8];
    float gv0 = gsh[R + g], gv1 = gsh[R + g + 8];

#pragma unroll 1
    for (int c = 0; c < 4; ++c) {
        float acc2[8][4];
#pragma unroll
        for (int j = 0; j < 8; ++j)
#pragma unroll
            for (int q = 0; q < 4; ++q) acc2[j][q] = 0.f;

#pragma unroll
        for (int s = 0; s < 4; ++s) {
#pragma unroll
            for (int jp = 0; jp < 4; ++jp) {
                uint32_t bh[4], bl[4];
                uint32_t bAddr = tb + B2HI +
                    ((uint32_t)((s * 16 + kBo) * SB2 + c * 64 + jp * 16 + nBo) << 1);
                ldm4t(bh, bAddr);
                ldm4t(bl, bAddr + (B2LO - B2HI));
                mma_bf16(acc2[2 * jp],     ah2[s], bh[0], bh[1]);
                mma_bf16(acc2[2 * jp],     ah2[s], bl[0], bl[1]);
                mma_bf16(acc2[2 * jp],     al2[s], bh[0], bh[1]);
                mma_bf16(acc2[2 * jp + 1], ah2[s], bh[2], bh[3]);
                mma_bf16(acc2[2 * jp + 1], ah2[s], bl[2], bl[3]);
                mma_bf16(acc2[2 * jp + 1], al2[s], bh[2], bh[3]);
            }
        }

        // epilogue chunk: g_part[a] = gate * (D2 + b2)
#pragma unroll
        for (int j = 0; j < 8; ++j) {
            int o0 = c * 64 + 8 * j + 2 * t;
            float2 bv = *(const float2*)(b2 + e * D_EMB + o0);
            if (aR0 >= 0) {
                float2 o;
                o.x = (acc2[j][0] + bv.x) * gv0;
                o.y = (acc2[j][1] + bv.y) * gv0;
                *(float2*)(g_part + (size_t)aR0 * D_EMB + o0) = o;
            }
            if (aR1 >= 0) {
                float2 o;
                o.x = (acc2[j][2] + bv.x) * gv1;
                o.y = (acc2[j][3] + bv.y) * gv1;
                *(float2*)(g_part + (size_t)aR1 * D_EMB + o0) = o;
            }
        }
    }
}

// ---------------- kernel C: combine (proven) -------------------------------------
__global__ void __launch_bounds__(256) k_combine(float* __restrict__ out) {
    __shared__ float red[256];
    int tid = threadIdx.x;
    size_t f4 = (size_t)blockIdx.x * 256 + tid;
    size_t t  = f4 >> 6;
    int    q  = (int)(f4 & 63);

    float4 aa = *((const float4*)(g_part + (t * 2)     * D_EMB) + q);
    float4 bb = *((const float4*)(g_part + (t * 2 + 1) * D_EMB) + q);
    float4 y;
    y.x = aa.x + bb.x; y.y = aa.y + bb.y; y.z = aa.z + bb.z; y.w = aa.w + bb.w;

    float kd = fabsf(y.x) + fabsf(y.y) + fabsf(y.z) + fabsf(y.w);

    float4 o;
    o.x = y.x * 0.5f; o.y = y.y * 0.5f; o.z = y.z * 0.5f; o.w = y.w * 0.5f;
    ((float4*)out)[f4] = o;

    red[tid] = kd;
    __syncthreads();
    for (int s = 128; s; s >>= 1) {
        if (tid < s) red[tid] += red[tid + s];
        __syncthreads();
    }
    if (tid == 0) g_kd_part[blockIdx.x] = red[0];
}

// ---------------- kernel D: finalize loss + reset counters (proven) --------------
__global__ void __launch_bounds__(256) k_final(float* __restrict__ out, int out_size) {
    __shared__ float red[256];
    __shared__ float impS[N_EXP * 256];
    int tid = threadIdx.x;

    float s = 0.f;
    for (int i = tid; i < NBLK_C; i += 256) s += g_kd_part[i];
    red[tid] = s;
    __syncthreads();
    for (int st = 128; st; st >>= 1) {
        if (tid < st) red[tid] += red[tid + st];
        __syncthreads();
    }
    float kd_total = red[0];
    __syncthreads();

    float imp[N_EXP];
#pragma unroll
    for (int e = 0; e < N_EXP; ++e) imp[e] = 0.f;
    for (int i = tid; i < NBLK_G; i += 256) {
#pragma unroll
        for (int e = 0; e < N_EXP; ++e)
            imp[e] += g_imp_part[i * N_EXP + e];
    }
#pragma unroll
    for (int e = 0; e < N_EXP; ++e) impS[e * 256 + tid] = imp[e];
    __syncthreads();
    for (int st = 128; st; st >>= 1) {
        if (tid < st)
#pragma unroll
            for (int e = 0; e < N_EXP; ++e)
                impS[e * 256 + tid] += impS[e * 256 + tid + st];
        __syncthreads();
    }

    if (tid == 0) {
        float iv[N_EXP], lv[N_EXP];
        float si = 0.f, sl = 0.f;
#pragma unroll
        for (int e = 0; e < N_EXP; ++e) {
            iv[e] = impS[e * 256];
            lv[e] = (float)g_count[e];
            si += iv[e]; sl += lv[e];
        }
        float mi = si / (float)N_EXP, ml = sl / (float)N_EXP;
        float vi = 0.f, vl = 0.f;
#pragma unroll
        for (int e = 0; e < N_EXP; ++e) {
            float di = iv[e] - mi; vi += di * di;
            float dl = lv[e] - ml; vl += dl * dl;
        }
        vi /= (float)(N_EXP - 1);
        vl /= (float)(N_EXP - 1);
        float aux = vi / (mi * mi + 1e-10f) + vl / (ml * ml + 1e-10f);
        float kd  = kd_total / (float)((size_t)T_TOK * D_EMB);
        if (out_size > T_TOK * D_EMB)
            out[(size_t)T_TOK * D_EMB] = aux + kd;
    }

    __syncthreads();
    if (tid < N_EXP) g_count[tid] = 0;
}

// ---------------- launch ----------------------------------------------------------
extern "C" void kernel_launch(void* const* d_in, const int* in_sizes, int n_in,
                              void* d_out, int out_size) {
    const float* x  = (const float*)d_in[0];
    const float* wg = (const float*)d_in[1];
    const float* w1 = (const float*)d_in[2];
    const float* b1 = (const float*)d_in[3];
    const float* w2 = (const float*)d_in[4];
    const float* b2 = (const float*)d_in[5];
    float* out = (float*)d_out;

    cudaFuncSetAttribute(k_ffn, cudaFuncAttributeMaxDynamicSharedMemorySize, SMEM_FFN);

    k_gate<<<NBLK_G, 256>>>(x, wg);
    dim3 gB(T_TOK / MTOK, N_EXP);
    k_ffn<<<gB, 256, SMEM_FFN>>>(x, w1, b1, w2, b2);
    k_combine<<<NBLK_C, 256>>>(out);
    k_final<<<1, 256>>>(out, out_size);
}